// round 3
// baseline (speedup 1.0000x reference)
#include <cuda_runtime.h>
#include <math.h>

#define NMAX 50000
#define EMAX 800000
#define HDIM 64

// ---------------- scratch (static __device__, no allocation) ----------------
__device__ float g_hyp[NMAX * HDIM];
__device__ float g_h0 [NMAX * HDIM];
__device__ float g_h1 [NMAX * HDIM];
__device__ float g_agg[NMAX * HDIM];
__device__ int   g_rowptr[NMAX + 1];
__device__ int   g_cnt[NMAX];
__device__ int   g_cur[NMAX];
__device__ int   g_adj[EMAX];

// ---------------- CSR build ----------------
__global__ void zero_kernel(int* cnt, int* cur, int N) {
    int i = blockIdx.x * blockDim.x + threadIdx.x;
    if (i < N) { cnt[i] = 0; cur[i] = 0; }
}

__global__ void count_kernel(const int* __restrict__ dst, int* cnt, int E) {
    int e = blockIdx.x * blockDim.x + threadIdx.x;
    if (e < E) atomicAdd(&cnt[dst[e]], 1);
}

// single-block exclusive scan: 1024 threads, sequential chunks + Hillis-Steele
__global__ void scan_kernel(const int* __restrict__ cnt, int* rowptr, int N) {
    __shared__ int s[1024];
    int t = threadIdx.x;
    int chunk = (N + 1023) / 1024;
    int beg = t * chunk;
    int end = min(beg + chunk, N);
    int sum = 0;
    for (int i = beg; i < end; i++) sum += cnt[i];
    s[t] = sum;
    __syncthreads();
    for (int off = 1; off < 1024; off <<= 1) {
        int v = (t >= off) ? s[t - off] : 0;
        __syncthreads();
        s[t] += v;
        __syncthreads();
    }
    int run = s[t] - sum;  // exclusive prefix for this chunk
    for (int i = beg; i < end; i++) { rowptr[i] = run; run += cnt[i]; }
    if (end == N) rowptr[N] = run;  // run == total for any thread with end==N
}

__global__ void fill_kernel(const int* __restrict__ src, const int* __restrict__ dst,
                            const int* __restrict__ rowptr, int* cur, int* adj, int E) {
    int e = blockIdx.x * blockDim.x + threadIdx.x;
    if (e < E) {
        int d = dst[e];
        int p = rowptr[d] + atomicAdd(&cur[d], 1);
        adj[p] = src[e];
    }
}

// ---------------- pull-based mean aggregation: warp per node ----------------
__global__ void agg_kernel(const float* __restrict__ h, float* __restrict__ agg,
                           const int* __restrict__ rowptr, const int* __restrict__ adj, int N) {
    int gw = (blockIdx.x * blockDim.x + threadIdx.x) >> 5;
    int lane = threadIdx.x & 31;
    if (gw >= N) return;
    int beg = rowptr[gw];
    int end = rowptr[gw + 1];
    float ax = 0.f, ay = 0.f;
#pragma unroll 4
    for (int e = beg; e < end; e++) {
        int s = __ldg(&adj[e]);
        float2 v = __ldg(((const float2*)(h + (size_t)s * HDIM)) + lane);
        ax += v.x; ay += v.y;
    }
    int deg = end - beg;
    float inv = 1.f / (float)max(deg, 1);
    float2 o; o.x = ax * inv; o.y = ay * inv;
    ((float2*)(agg + (size_t)gw * HDIM))[lane] = o;
}

// ---------------- generic tiled GEMM: out[N,64] = A0@W0 + A1@W1 + b (+addv)(act)
// A0: [N,K0], A1: [N,K1] (nullable), W0: [K0,64], W1: [K1,64]
// act: 0 none, 1 relu, 2 tanh
__global__ void gemm_n64(const float* __restrict__ A0, int K0,
                         const float* __restrict__ A1, int K1,
                         const float* __restrict__ W0, const float* __restrict__ W1,
                         const float* __restrict__ bias,
                         const float* __restrict__ addv,
                         float* __restrict__ out, int N, int act) {
    __shared__ float As[128 * 68];  // transposed A tile [K][64], pad 68
    const int node0 = blockIdx.x * 64;
    const int tid = threadIdx.x;
    const int K = K0 + K1;

    // stage A tile transposed (coalesced gmem reads)
    for (int i = tid; i < 64 * K; i += 256) {
        int nl = i / K, k = i - nl * K;
        int n = node0 + nl;
        float v = 0.f;
        if (n < N) v = (k < K0) ? A0[(size_t)n * K0 + k] : A1[(size_t)n * K1 + (k - K0)];
        As[k * 68 + nl] = v;
    }
    __syncthreads();

    const int fr = tid & 15;   // 4 features fr*4..+3
    const int nr = tid >> 4;   // 4 nodes   nr*4..+3
    float acc[4][4];
#pragma unroll
    for (int i = 0; i < 4; i++)
#pragma unroll
        for (int j = 0; j < 4; j++) acc[i][j] = 0.f;

#pragma unroll 4
    for (int k = 0; k < K0; k++) {
        float4 av = *(const float4*)&As[k * 68 + nr * 4];
        float4 wv = __ldg((const float4*)&W0[(size_t)k * 64 + fr * 4]);
        float a[4] = {av.x, av.y, av.z, av.w};
        float w[4] = {wv.x, wv.y, wv.z, wv.w};
#pragma unroll
        for (int i = 0; i < 4; i++)
#pragma unroll
            for (int j = 0; j < 4; j++) acc[i][j] += a[i] * w[j];
    }
#pragma unroll 4
    for (int k = 0; k < K1; k++) {
        float4 av = *(const float4*)&As[(K0 + k) * 68 + nr * 4];
        float4 wv = __ldg((const float4*)&W1[(size_t)k * 64 + fr * 4]);
        float a[4] = {av.x, av.y, av.z, av.w};
        float w[4] = {wv.x, wv.y, wv.z, wv.w};
#pragma unroll
        for (int i = 0; i < 4; i++)
#pragma unroll
            for (int j = 0; j < 4; j++) acc[i][j] += a[i] * w[j];
    }

    float b0 = bias[fr * 4 + 0], b1 = bias[fr * 4 + 1];
    float b2 = bias[fr * 4 + 2], b3 = bias[fr * 4 + 3];
#pragma unroll
    for (int i = 0; i < 4; i++) {
        int n = node0 + nr * 4 + i;
        if (n < N) {
            float4 v;
            v.x = acc[i][0] + b0; v.y = acc[i][1] + b1;
            v.z = acc[i][2] + b2; v.w = acc[i][3] + b3;
            if (addv) {
                float4 a = __ldg((const float4*)&addv[(size_t)n * 64 + fr * 4]);
                v.x += a.x; v.y += a.y; v.z += a.z; v.w += a.w;
            }
            if (act == 1) {
                v.x = fmaxf(v.x, 0.f); v.y = fmaxf(v.y, 0.f);
                v.z = fmaxf(v.z, 0.f); v.w = fmaxf(v.w, 0.f);
            } else if (act == 2) {
                v.x = tanhf(v.x); v.y = tanhf(v.y);
                v.z = tanhf(v.z); v.w = tanhf(v.w);
            }
            *(float4*)&out[(size_t)n * 64 + fr * 4] = v;
        }
    }
}

// ---------------- final: emb = h@W_last + b; log_softmax -----------------
__global__ void final_kernel(const float* __restrict__ h, const float* __restrict__ W,
                             const float* __restrict__ b, float* __restrict__ out,
                             int N, int out_size) {
    __shared__ float Ws[64 * 40];
    __shared__ float bs[40];
    int tid = threadIdx.x;
    for (int i = tid; i < 64 * 40; i += 256) Ws[i] = W[i];
    if (tid < 40) bs[tid] = b[tid];
    __syncthreads();

    int n = blockIdx.x * 256 + tid;
    if (n >= N) return;

    float acc[40];
#pragma unroll
    for (int c = 0; c < 40; c++) acc[c] = bs[c];
    const float* hr = h + (size_t)n * 64;
#pragma unroll 4
    for (int k = 0; k < 64; k++) {
        float hv = __ldg(&hr[k]);
#pragma unroll
        for (int c = 0; c < 40; c++) acc[c] += hv * Ws[k * 40 + c];
    }
    float mx = acc[0];
#pragma unroll
    for (int c = 1; c < 40; c++) mx = fmaxf(mx, acc[c]);
    float sum = 0.f;
#pragma unroll
    for (int c = 0; c < 40; c++) sum += expf(acc[c] - mx);
    float lse = mx + logf(sum);

    size_t base = (size_t)n * 40;
    size_t base2 = (size_t)N * 40 + base;
#pragma unroll
    for (int c = 0; c < 40; c++) {
        if (base + c < (size_t)out_size) out[base + c] = acc[c];
        if (base2 + c < (size_t)out_size) out[base2 + c] = acc[c] - lse;
    }
}

// ---------------- launch ----------------
extern "C" void kernel_launch(void* const* d_in, const int* in_sizes, int n_in,
                              void* d_out, int out_size) {
    const float* x_h    = (const float*)d_in[0];
    const float* pos    = (const float*)d_in[1];
    const int*   ei     = (const int*)  d_in[2];
    const float* W_pos  = (const float*)d_in[3];
    const float* b_pos  = (const float*)d_in[4];
    const float* W_init = (const float*)d_in[5];
    const float* b_init = (const float*)d_in[6];
    const float* W_l    = (const float*)d_in[7];
    const float* W_r    = (const float*)d_in[8];
    const float* b_conv = (const float*)d_in[9];
    const float* W_last = (const float*)d_in[10];
    const float* b_last = (const float*)d_in[11];

    int N = in_sizes[0] / 128;
    int E = in_sizes[2] / 2;

    float *hyp, *h0, *h1, *agg;
    int *rowptr, *cnt, *cur, *adj;
    cudaGetSymbolAddress((void**)&hyp,    g_hyp);
    cudaGetSymbolAddress((void**)&h0,     g_h0);
    cudaGetSymbolAddress((void**)&h1,     g_h1);
    cudaGetSymbolAddress((void**)&agg,    g_agg);
    cudaGetSymbolAddress((void**)&rowptr, g_rowptr);
    cudaGetSymbolAddress((void**)&cnt,    g_cnt);
    cudaGetSymbolAddress((void**)&cur,    g_cur);
    cudaGetSymbolAddress((void**)&adj,    g_adj);

    const int* src = ei;
    const int* dst = ei + E;

    // CSR build
    zero_kernel <<<(N + 255) / 256, 256>>>(cnt, cur, N);
    count_kernel<<<(E + 255) / 256, 256>>>(dst, cnt, E);
    scan_kernel <<<1, 1024>>>(cnt, rowptr, N);
    fill_kernel <<<(E + 255) / 256, 256>>>(src, dst, rowptr, cur, adj, E);

    int gb = (N + 63) / 64;
    // hyp_pos = tanh(pos @ W_pos + b_pos)
    gemm_n64<<<gb, 256>>>(pos, 16, nullptr, 0, W_pos, nullptr, b_pos, nullptr, hyp, N, 2);
    // h0 = x_h @ W_init + b_init
    gemm_n64<<<gb, 256>>>(x_h, 128, nullptr, 0, W_init, nullptr, b_init, nullptr, h0, N, 0);

    float* hc = h0;
    float* hn = h1;
    for (int l = 0; l < 3; l++) {
        agg_kernel<<<(N + 7) / 8, 256>>>(hc, agg, rowptr, adj, N);
        const float* Wl = W_l + (size_t)l * 64 * 64;
        const float* Wr = W_r + (size_t)l * 64 * 64;
        const float* bc = b_conv + (size_t)l * 64;
        const float* av = (l < 2) ? hyp : nullptr;
        int act = (l < 2) ? 1 : 0;
        gemm_n64<<<gb, 256>>>(agg, 64, hc, 64, Wl, Wr, bc, av, hn, N, act);
        float* t = hc; hc = hn; hn = t;
    }

    final_kernel<<<(N + 255) / 256, 256>>>(hc, W_last, b_last, (float*)d_out, N, out_size);
}

// round 6
// speedup vs baseline: 1.2852x; 1.2852x over previous
#include <cuda_runtime.h>
#include <math.h>

#define NMAX 50000
#define EMAX 800000
#define HDIM 64

// ---------------- scratch (static __device__, no allocation) ----------------
__device__ float g_hyp[NMAX * HDIM];
__device__ float g_h0 [NMAX * HDIM];
__device__ float g_h1 [NMAX * HDIM];
__device__ float g_y  [NMAX * HDIM];
__device__ float g_z  [NMAX * HDIM];
__device__ int   g_rowptr[NMAX + 1];
__device__ int   g_cnt[NMAX];
__device__ int   g_cur[NMAX];
__device__ int   g_adj[EMAX];

// ---------------- CSR build ----------------
__global__ void zero_kernel(int* cnt, int* cur, int N) {
    int i = blockIdx.x * blockDim.x + threadIdx.x;
    if (i < N) { cnt[i] = 0; cur[i] = 0; }
}

__global__ void count_kernel(const int* __restrict__ dst, int* cnt, int E) {
    int e = blockIdx.x * blockDim.x + threadIdx.x;
    if (e < E) atomicAdd(&cnt[dst[e]], 1);
}

// single-block exclusive scan: 1024 threads, sequential chunks + Hillis-Steele
__global__ void scan_kernel(const int* __restrict__ cnt, int* rowptr, int N) {
    __shared__ int s[1024];
    int t = threadIdx.x;
    int chunk = (N + 1023) / 1024;
    int beg = t * chunk;
    int end = min(beg + chunk, N);
    int sum = 0;
    for (int i = beg; i < end; i++) sum += cnt[i];
    s[t] = sum;
    __syncthreads();
    for (int off = 1; off < 1024; off <<= 1) {
        int v = (t >= off) ? s[t - off] : 0;
        __syncthreads();
        s[t] += v;
        __syncthreads();
    }
    int run = s[t] - sum;  // exclusive prefix for this chunk
    for (int i = beg; i < end; i++) { rowptr[i] = run; run += cnt[i]; }
    if (end == N) rowptr[N] = run;
}

__global__ void fill_kernel(const int* __restrict__ src, const int* __restrict__ dst,
                            const int* __restrict__ rowptr, int* cur, int* adj, int E) {
    int e = blockIdx.x * blockDim.x + threadIdx.x;
    if (e < E) {
        int d = dst[e];
        int p = rowptr[d] + atomicAdd(&cur[d], 1);
        adj[p] = src[e];
    }
}

// ---------------- dual GEMM: Y = A@Wl ; Z = A@Wr + b (+hyp) -----------------
// A:[N,64], Wl/Wr:[64,64] row-major. Block: 64 nodes x 128 outputs, 128 thr.
__global__ __launch_bounds__(128, 4)
void gemm_dual(const float* __restrict__ A,
               const float* __restrict__ Wl, const float* __restrict__ Wr,
               const float* __restrict__ bias, const float* __restrict__ hyp,
               float* __restrict__ Y, float* __restrict__ Z, int N) {
    __shared__ float As[64 * 65];    // [node][k], row pad 65 (conflict-free k reads)
    __shared__ float Ws[64 * 128];   // [k][j], j<64 -> Wl col, j>=64 -> Wr col
    const int node0 = blockIdx.x * 64;
    const int tid = threadIdx.x;

    // stage Ws: 2048 float4 / 128 threads = 16 each (coalesced)
    {
        const float4* Wl4 = (const float4*)Wl;
        const float4* Wr4 = (const float4*)Wr;
        float4* Ws4 = (float4*)Ws;
#pragma unroll
        for (int r = 0; r < 16; r++) {
            int idx = r * 128 + tid;          // f4 index into [64][32]
            int k = idx >> 5, j4 = idx & 31;
            Ws4[idx] = (j4 < 16) ? __ldg(&Wl4[k * 16 + j4])
                                 : __ldg(&Wr4[k * 16 + (j4 - 16)]);
        }
    }
    // stage As: 64 nodes x 16 float4 = 1024 f4 / 128 threads = 8 each
    {
#pragma unroll
        for (int r = 0; r < 8; r++) {
            int idx = r * 128 + tid;
            int nl = idx >> 4, c4 = idx & 15;
            int n = node0 + nl;
            float4 v = make_float4(0.f, 0.f, 0.f, 0.f);
            if (n < N) v = __ldg((const float4*)(A + (size_t)n * 64) + c4);
            float* d = &As[nl * 65 + c4 * 4];
            d[0] = v.x; d[1] = v.y; d[2] = v.z; d[3] = v.w;
        }
    }
    __syncthreads();

    const int fr = tid & 15;   // 8 feats fr*8..+7  (of 128 = [Y|Z])
    const int nr = tid >> 4;   // 8 nodes nr*8..+7  (of 64)
    float acc[8][8];
#pragma unroll
    for (int i = 0; i < 8; i++)
#pragma unroll
        for (int j = 0; j < 8; j++) acc[i][j] = 0.f;

    const float* asb = &As[nr * 8 * 65];
#pragma unroll 4
    for (int k = 0; k < 64; k++) {
        float4 w0 = *(const float4*)&Ws[k * 128 + fr * 8];
        float4 w1 = *(const float4*)&Ws[k * 128 + fr * 8 + 4];
        float w[8] = {w0.x, w0.y, w0.z, w0.w, w1.x, w1.y, w1.z, w1.w};
        float a[8];
#pragma unroll
        for (int i = 0; i < 8; i++) a[i] = asb[i * 65 + k];
#pragma unroll
        for (int i = 0; i < 8; i++)
#pragma unroll
            for (int j = 0; j < 8; j++) acc[i][j] += a[i] * w[j];
    }

    if (fr < 8) {
        // Y part: feats fr*8..+7, no bias
        int f0 = fr * 8;
#pragma unroll
        for (int i = 0; i < 8; i++) {
            int n = node0 + nr * 8 + i;
            if (n >= N) break;
            float4 v0 = make_float4(acc[i][0], acc[i][1], acc[i][2], acc[i][3]);
            float4 v1 = make_float4(acc[i][4], acc[i][5], acc[i][6], acc[i][7]);
            *(float4*)&Y[(size_t)n * 64 + f0]     = v0;
            *(float4*)&Y[(size_t)n * 64 + f0 + 4] = v1;
        }
    } else {
        // Z part: feats (fr-8)*8..+7, + bias (+hyp)
        int f0 = (fr - 8) * 8;
        float b[8];
#pragma unroll
        for (int j = 0; j < 8; j++) b[j] = __ldg(&bias[f0 + j]);
#pragma unroll
        for (int i = 0; i < 8; i++) {
            int n = node0 + nr * 8 + i;
            if (n >= N) break;
            float v[8];
#pragma unroll
            for (int j = 0; j < 8; j++) v[j] = acc[i][j] + b[j];
            if (hyp) {
                float4 h0v = __ldg((const float4*)&hyp[(size_t)n * 64 + f0]);
                float4 h1v = __ldg((const float4*)&hyp[(size_t)n * 64 + f0 + 4]);
                v[0] += h0v.x; v[1] += h0v.y; v[2] += h0v.z; v[3] += h0v.w;
                v[4] += h1v.x; v[5] += h1v.y; v[6] += h1v.z; v[7] += h1v.w;
            }
            *(float4*)&Z[(size_t)n * 64 + f0]     = make_float4(v[0], v[1], v[2], v[3]);
            *(float4*)&Z[(size_t)n * 64 + f0 + 4] = make_float4(v[4], v[5], v[6], v[7]);
        }
    }
}

// ------------- fused gather-mean + Z + act: out = act(mean(Y[src]) + Z) -----
__global__ void agg_epi(const float* __restrict__ Y, const float* __restrict__ Z,
                        float* __restrict__ out,
                        const int* __restrict__ rowptr, const int* __restrict__ adj,
                        int N, int relu) {
    int gw = (blockIdx.x * blockDim.x + threadIdx.x) >> 5;
    int lane = threadIdx.x & 31;
    if (gw >= N) return;
    int beg = rowptr[gw];
    int end = rowptr[gw + 1];
    float ax = 0.f, ay = 0.f;
#pragma unroll 4
    for (int e = beg; e < end; e++) {
        int s = __ldg(&adj[e]);
        float2 v = __ldg(((const float2*)(Y + (size_t)s * HDIM)) + lane);
        ax += v.x; ay += v.y;
    }
    float inv = 1.f / (float)max(end - beg, 1);
    float2 z = __ldg(((const float2*)(Z + (size_t)gw * HDIM)) + lane);
    float ox = ax * inv + z.x;
    float oy = ay * inv + z.y;
    if (relu) { ox = fmaxf(ox, 0.f); oy = fmaxf(oy, 0.f); }
    ((float2*)(out + (size_t)gw * HDIM))[lane] = make_float2(ox, oy);
}

// ---------------- generic tiled GEMM (init / pos): out[N,64] = A@W + b (act)
__global__ void gemm_n64(const float* __restrict__ A0, int K0,
                         const float* __restrict__ W0,
                         const float* __restrict__ bias,
                         float* __restrict__ out, int N, int act) {
    __shared__ float As[128 * 68];
    const int node0 = blockIdx.x * 64;
    const int tid = threadIdx.x;
    const int K = K0;

    for (int i = tid; i < 64 * K; i += 256) {
        int nl = i / K, k = i - nl * K;
        int n = node0 + nl;
        float v = 0.f;
        if (n < N) v = A0[(size_t)n * K0 + k];
        As[k * 68 + nl] = v;
    }
    __syncthreads();

    const int fr = tid & 15;
    const int nr = tid >> 4;
    float acc[4][4];
#pragma unroll
    for (int i = 0; i < 4; i++)
#pragma unroll
        for (int j = 0; j < 4; j++) acc[i][j] = 0.f;

#pragma unroll 4
    for (int k = 0; k < K; k++) {
        float4 av = *(const float4*)&As[k * 68 + nr * 4];
        float4 wv = __ldg((const float4*)&W0[(size_t)k * 64 + fr * 4]);
        float a[4] = {av.x, av.y, av.z, av.w};
        float w[4] = {wv.x, wv.y, wv.z, wv.w};
#pragma unroll
        for (int i = 0; i < 4; i++)
#pragma unroll
            for (int j = 0; j < 4; j++) acc[i][j] += a[i] * w[j];
    }

    float b0 = bias[fr * 4 + 0], b1 = bias[fr * 4 + 1];
    float b2 = bias[fr * 4 + 2], b3 = bias[fr * 4 + 3];
#pragma unroll
    for (int i = 0; i < 4; i++) {
        int n = node0 + nr * 4 + i;
        if (n < N) {
            float4 v;
            v.x = acc[i][0] + b0; v.y = acc[i][1] + b1;
            v.z = acc[i][2] + b2; v.w = acc[i][3] + b3;
            if (act == 2) {
                v.x = tanhf(v.x); v.y = tanhf(v.y);
                v.z = tanhf(v.z); v.w = tanhf(v.w);
            }
            *(float4*)&out[(size_t)n * 64 + fr * 4] = v;
        }
    }
}

// ---------------- final: emb = h@W_last + b; log_softmax -----------------
__global__ void final_kernel(const float* __restrict__ h, const float* __restrict__ W,
                             const float* __restrict__ b, float* __restrict__ out,
                             int N, int out_size) {
    __shared__ float Ws[64 * 40];
    __shared__ float bs[40];
    int tid = threadIdx.x;
    for (int i = tid; i < 64 * 40; i += 256) Ws[i] = W[i];
    if (tid < 40) bs[tid] = b[tid];
    __syncthreads();

    int n = blockIdx.x * 256 + tid;
    if (n >= N) return;

    float acc[40];
#pragma unroll
    for (int c = 0; c < 40; c++) acc[c] = bs[c];
    const float* hr = h + (size_t)n * 64;
#pragma unroll 4
    for (int k = 0; k < 64; k++) {
        float hv = __ldg(&hr[k]);
#pragma unroll
        for (int c = 0; c < 40; c++) acc[c] += hv * Ws[k * 40 + c];
    }
    float mx = acc[0];
#pragma unroll
    for (int c = 1; c < 40; c++) mx = fmaxf(mx, acc[c]);
    float sum = 0.f;
#pragma unroll
    for (int c = 0; c < 40; c++) sum += expf(acc[c] - mx);
    float lse = mx + logf(sum);

    size_t base = (size_t)n * 40;
    size_t base2 = (size_t)N * 40 + base;
#pragma unroll
    for (int c = 0; c < 40; c++) {
        if (base + c < (size_t)out_size) out[base + c] = acc[c];
        if (base2 + c < (size_t)out_size) out[base2 + c] = acc[c] - lse;
    }
}

// ---------------- launch ----------------
extern "C" void kernel_launch(void* const* d_in, const int* in_sizes, int n_in,
                              void* d_out, int out_size) {
    const float* x_h    = (const float*)d_in[0];
    const float* pos    = (const float*)d_in[1];
    const int*   ei     = (const int*)  d_in[2];
    const float* W_pos  = (const float*)d_in[3];
    const float* b_pos  = (const float*)d_in[4];
    const float* W_init = (const float*)d_in[5];
    const float* b_init = (const float*)d_in[6];
    const float* W_l    = (const float*)d_in[7];
    const float* W_r    = (const float*)d_in[8];
    const float* b_conv = (const float*)d_in[9];
    const float* W_last = (const float*)d_in[10];
    const float* b_last = (const float*)d_in[11];

    int N = in_sizes[0] / 128;
    int E = in_sizes[2] / 2;

    float *hyp, *h0, *h1, *ybuf, *zbuf;
    int *rowptr, *cnt, *cur, *adj;
    cudaGetSymbolAddress((void**)&hyp,    g_hyp);
    cudaGetSymbolAddress((void**)&h0,     g_h0);
    cudaGetSymbolAddress((void**)&h1,     g_h1);
    cudaGetSymbolAddress((void**)&ybuf,   g_y);
    cudaGetSymbolAddress((void**)&zbuf,   g_z);
    cudaGetSymbolAddress((void**)&rowptr, g_rowptr);
    cudaGetSymbolAddress((void**)&cnt,    g_cnt);
    cudaGetSymbolAddress((void**)&cur,    g_cur);
    cudaGetSymbolAddress((void**)&adj,    g_adj);

    const int* src = ei;
    const int* dst = ei + E;

    // CSR build
    zero_kernel <<<(N + 255) / 256, 256>>>(cnt, cur, N);
    count_kernel<<<(E + 255) / 256, 256>>>(dst, cnt, E);
    scan_kernel <<<1, 1024>>>(cnt, rowptr, N);
    fill_kernel <<<(E + 255) / 256, 256>>>(src, dst, rowptr, cur, adj, E);

    int gb64 = (N + 63) / 64;
    // hyp = tanh(pos @ W_pos + b_pos)
    gemm_n64<<<gb64, 256>>>(pos, 16, W_pos, b_pos, hyp, N, 2);
    // h0 = x_h @ W_init + b_init
    gemm_n64<<<gb64, 256>>>(x_h, 128, W_init, b_init, h0, N, 0);

    float* hc = h0;
    float* hn = h1;
    for (int l = 0; l < 3; l++) {
        const float* Wl = W_l + (size_t)l * 64 * 64;
        const float* Wr = W_r + (size_t)l * 64 * 64;
        const float* bc = b_conv + (size_t)l * 64;
        const float* av = (l < 2) ? hyp : nullptr;
        int act = (l < 2) ? 1 : 0;
        // Y = hc @ Wl ; Z = hc @ Wr + b (+hyp)
        gemm_dual<<<gb64, 128>>>(hc, Wl, Wr, bc, av, ybuf, zbuf, N);
        // hn = act(mean(Y[src]) + Z)
        agg_epi<<<(N + 7) / 8, 256>>>(ybuf, zbuf, hn, rowptr, adj, N, act);
        float* t = hc; hc = hn; hn = t;
    }

    final_kernel<<<(N + 255) / 256, 256>>>(hc, W_last, b_last, (float*)d_out, N, out_size);
}